// round 6
// baseline (speedup 1.0000x reference)
#include <cuda_runtime.h>
#include <mma.h>

using namespace nvcuda;

#define N_NODES 100000
#define N_EDGES 1600000
#define IN_DIM  128
#define HID_DIM 64
#define GB      782          // ceil(N_NODES/128) gemm tile blocks
#define CB      1024         // count blocks riding along with gemm1
#define SB      98           // scan blocks (ceil(N_NODES/1024)), < 148 SMs
#define AGG_BLOCKS (2 * N_NODES / 8)   // 25000: warp per (node, half)

// ------------------------- device scratch (no allocs allowed) ---------------
// d_cnt / d_flag start zeroed (BSS) and are re-zeroed at the end of every call
// by the final aggregation kernel, so every invocation sees identical state.
__device__ int   d_cnt [N_NODES];                       // edge count per dst
__device__ int   d_rs  [N_NODES];                       // CSR row starts
__device__ int   d_fill[N_NODES];                       // fill cursors
__device__ float d_dinv[N_NODES];                       // 1/sqrt(deg) (deg=cnt+1)
__device__ int   d_csr [N_EDGES];                       // src ids bucketed by dst
__device__ __align__(16) float d_bufA[(size_t)N_NODES * HID_DIM]; // GEMM out
__device__ __align__(16) float d_bufB[(size_t)N_NODES * HID_DIM]; // activation
__device__ int   d_agg [SB];                            // scan block aggregates
__device__ int   d_flag[SB];                            // publish flags

// ------------------------- TF32 GEMM (+ optional fused degree count) --------
#define SA_LD 40
#define SO_LD 68
#define SW_ELE (32 * 64)
#define SMEM_FLOATS 8704

template <int K, bool A_IS_PARAM, bool COUNT>
__global__ __launch_bounds__(256) void k_gemm_tf32(const float* __restrict__ Aparam,
                                                   const float* __restrict__ W,
                                                   const int* __restrict__ dst) {
    __shared__ __align__(16) float smem[SMEM_FLOATS];
    if (COUNT && blockIdx.x >= GB) {                    // fused degree count
        int e0 = (blockIdx.x - GB) * 256 + threadIdx.x;
        for (int e = e0; e < N_EDGES; e += CB * 256)
            atomicAdd(&d_cnt[dst[e]], 1);
        return;
    }
    float* sW = smem;                                   // 32 x 64
    float* sA = smem + SW_ELE;                          // 128 x SA_LD
    const float* A = A_IS_PARAM ? Aparam : (const float*)d_bufB;

    int tid    = threadIdx.x;
    int warpId = tid >> 5;
    int r0     = blockIdx.x * 128;
    int wrow   = warpId * 16;

    wmma::fragment<wmma::matrix_a, 16, 16, 8, wmma::precision::tf32, wmma::row_major> fa;
    wmma::fragment<wmma::matrix_b, 16, 16, 8, wmma::precision::tf32, wmma::row_major> fb;
    wmma::fragment<wmma::accumulator, 16, 16, 8, float> fc[4];
#pragma unroll
    for (int n = 0; n < 4; ++n) wmma::fill_fragment(fc[n], 0.0f);

    for (int kc = 0; kc < K; kc += 32) {
#pragma unroll
        for (int u = 0; u < 2; ++u) {                   // W chunk: 32x64
            int idx = u * 256 + tid;
            float4 v = *(const float4*)&W[(size_t)kc * 64 + idx * 4];
            *(float4*)&sW[idx * 4] = v;
        }
#pragma unroll
        for (int u = 0; u < 4; ++u) {                   // A chunk: 128x32
            int idx = u * 256 + tid;
            int row = idx >> 3;
            int c4  = idx & 7;
            int r   = r0 + row;
            float4 v = make_float4(0.f, 0.f, 0.f, 0.f);
            if (r < N_NODES)
                v = *(const float4*)&A[(size_t)r * K + kc + c4 * 4];
            *(float4*)&sA[row * SA_LD + c4 * 4] = v;
        }
        __syncthreads();
#pragma unroll
        for (int kk = 0; kk < 32; kk += 8) {
            wmma::load_matrix_sync(fa, &sA[wrow * SA_LD + kk], SA_LD);
#pragma unroll
            for (int i = 0; i < fa.num_elements; ++i)
                fa.x[i] = wmma::__float_to_tf32(fa.x[i]);
#pragma unroll
            for (int n = 0; n < 4; ++n) {
                wmma::load_matrix_sync(fb, &sW[kk * 64 + n * 16], 64);
#pragma unroll
                for (int i = 0; i < fb.num_elements; ++i)
                    fb.x[i] = wmma::__float_to_tf32(fb.x[i]);
                wmma::mma_sync(fc[n], fa, fb, fc[n]);
            }
        }
        __syncthreads();
    }

    float* sOut = smem;                                 // 128 x SO_LD
#pragma unroll
    for (int n = 0; n < 4; ++n)
        wmma::store_matrix_sync(&sOut[wrow * SO_LD + n * 16], fc[n], SO_LD,
                                wmma::mem_row_major);
    __syncthreads();
#pragma unroll
    for (int u = 0; u < 8; ++u) {
        int idx = u * 256 + tid;
        int row = idx >> 4;
        int c4  = idx & 15;
        int r   = r0 + row;
        if (r < N_NODES) {
            float4 v = *(float4*)&sOut[row * SO_LD + c4 * 4];
            *(float4*)&d_bufA[(size_t)r * 64 + c4 * 4] = v;
        }
    }
}

// ------------------------- single-pass scan (row starts + dinv) -------------
__global__ __launch_bounds__(256) void k_scan() {
    __shared__ int sm[256];
    __shared__ int sBase;
    int tid = threadIdx.x, bid = blockIdx.x;
    int base = bid * 1024 + tid * 4;
    int c[4], v[4];
    int s = 0;
#pragma unroll
    for (int j = 0; j < 4; ++j) {
        int idx = base + j;
        c[j] = (idx < N_NODES) ? d_cnt[idx] : 0;
        v[j] = s; s += c[j];
    }
    sm[tid] = s;
    __syncthreads();
#pragma unroll
    for (int off = 1; off < 256; off <<= 1) {
        int t = (tid >= off) ? sm[tid - off] : 0;
        __syncthreads();
        sm[tid] += t;
        __syncthreads();
    }
    if (tid == 0) {                                     // publish aggregate
        d_agg[bid] = sm[255];
        __threadfence();
        *((volatile int*)&d_flag[bid]) = 1;
    }
    if (tid < 32) {                                     // lookback: sum preds
        int acc = 0;
        for (int i = tid; i < bid; i += 32) {
            while (*((volatile int*)&d_flag[i]) == 0) {}
            acc += *((volatile int*)&d_agg[i]);
        }
#pragma unroll
        for (int off = 16; off; off >>= 1)
            acc += __shfl_down_sync(0xffffffffu, acc, off);
        if (tid == 0) sBase = acc;
    }
    __syncthreads();
    int excl = (tid == 0) ? 0 : sm[tid - 1];
    int off0 = sBase + excl;
#pragma unroll
    for (int j = 0; j < 4; ++j) {
        int idx = base + j;
        if (idx < N_NODES) {
            int r = off0 + v[j];
            d_rs[idx]   = r;
            d_fill[idx] = r;
            d_dinv[idx] = rsqrtf((float)(c[j] + 1));    // +1: self-loop
        }
    }
}

// ------------------------- CSR fill -----------------------------------------
__global__ void k_fill(const int* __restrict__ src,
                       const int* __restrict__ dst) {
    int e = blockIdx.x * blockDim.x + threadIdx.x;
    if (e < N_EDGES) {
        int d = dst[e];
        int p = atomicAdd(&d_fill[d], 1);
        d_csr[p] = src[e];
    }
}

// ------------------------- pull aggregation (warp per node-half) ------------
// unit u = node*2 + half; warp's lane owns dim d = half*32+lane (4B loads:
// one exact 128B line per gather). out[i] = relu(dinv_i*(sum dinv_s*g[s] +
// dinv_i*g[i]) + b). FINAL: warp-pair combines halves for the 64->1 FC head.
template <bool FINAL>
__global__ __launch_bounds__(256) void k_aggr(const float* __restrict__ bias,
                                              const float* __restrict__ Wfc,
                                              const float* __restrict__ bfc,
                                              float* __restrict__ outp) {
    __shared__ float sP[8];
    int wId  = threadIdx.x >> 5;
    int lane = threadIdx.x & 31;
    int u    = blockIdx.x * 8 + wId;                    // exact: 2*N_NODES units
    int node = u >> 1;
    int half = u & 1;
    int d    = half * 32 + lane;
    const float* __restrict__ g = d_bufA;

    int   start = d_rs[node];
    int   cnt   = d_cnt[node];
    float dvn   = d_dinv[node];

    float a0 = dvn * g[(size_t)node * 64 + d];          // self-loop term
    float a1 = 0.f, a2 = 0.f, a3 = 0.f;

    int t = 0;
    for (; t + 8 <= cnt; t += 8) {                      // 8-deep MLP
        int s0 = d_csr[start + t + 0];
        int s1 = d_csr[start + t + 1];
        int s2 = d_csr[start + t + 2];
        int s3 = d_csr[start + t + 3];
        int s4 = d_csr[start + t + 4];
        int s5 = d_csr[start + t + 5];
        int s6 = d_csr[start + t + 6];
        int s7 = d_csr[start + t + 7];
        float w0 = d_dinv[s0], w1 = d_dinv[s1], w2 = d_dinv[s2], w3 = d_dinv[s3];
        float w4 = d_dinv[s4], w5 = d_dinv[s5], w6 = d_dinv[s6], w7 = d_dinv[s7];
        float v0 = g[(size_t)s0 * 64 + d];
        float v1 = g[(size_t)s1 * 64 + d];
        float v2 = g[(size_t)s2 * 64 + d];
        float v3 = g[(size_t)s3 * 64 + d];
        float v4 = g[(size_t)s4 * 64 + d];
        float v5 = g[(size_t)s5 * 64 + d];
        float v6 = g[(size_t)s6 * 64 + d];
        float v7 = g[(size_t)s7 * 64 + d];
        a0 = fmaf(w0, v0, a0); a1 = fmaf(w1, v1, a1);
        a2 = fmaf(w2, v2, a2); a3 = fmaf(w3, v3, a3);
        a0 = fmaf(w4, v4, a0); a1 = fmaf(w5, v5, a1);
        a2 = fmaf(w6, v6, a2); a3 = fmaf(w7, v7, a3);
    }
    for (; t < cnt; ++t) {
        int s = d_csr[start + t];
        a0 = fmaf(d_dinv[s], g[(size_t)s * 64 + d], a0);
    }

    float h = fmaf(dvn, (a0 + a1) + (a2 + a3), bias[d]);
    h = fmaxf(h, 0.f);

    if (!FINAL) {
        d_bufB[(size_t)node * 64 + d] = h;              // coalesced 128B/warp
    } else {
        float p = h * Wfc[d];
#pragma unroll
        for (int off = 16; off; off >>= 1)
            p += __shfl_down_sync(0xffffffffu, p, off);
        if (lane == 0) sP[wId] = p;
        __syncthreads();
        if (half == 0 && lane == 0)
            outp[node] = sP[wId] + sP[wId + 1] + bfc[0];
        // restore invariant state (after sync: all reads of d_cnt are done)
        if (half == 1 && lane == 1) d_cnt[node] = 0;
        if (half == 1 && lane == 2 && node < SB) d_flag[node] = 0;
    }
}

// ------------------------- launch ------------------------------------------
extern "C" void kernel_launch(void* const* d_in, const int* in_sizes, int n_in,
                              void* d_out, int out_size) {
    const float* x    = (const float*)d_in[0];
    const int*   ei   = (const int*)d_in[1];   // JAX x64 disabled: int32
    const float* W1   = (const float*)d_in[2];
    const float* b1   = (const float*)d_in[3];
    const float* W2   = (const float*)d_in[4];
    const float* b2   = (const float*)d_in[5];
    const float* Wfc  = (const float*)d_in[6];
    const float* bfc  = (const float*)d_in[7];
    float*       out  = (float*)d_out;

    const int* srcp = ei;              // edge_index[0]
    const int* dstp = ei + N_EDGES;    // edge_index[1]

    const int EB = (N_EDGES + 255) / 256;

    // gemm1 fused with degree count (independent work shares one launch)
    k_gemm_tf32<IN_DIM, true, true ><<<GB + CB, 256>>>(x, W1, dstp);
    k_scan<<<SB, 256>>>();
    k_fill<<<EB, 256>>>(srcp, dstp);
    k_aggr<false><<<AGG_BLOCKS, 256>>>(b1, Wfc, bfc, out);
    // layer 2 + fused FC head (+ state restore)
    k_gemm_tf32<HID_DIM, false, false><<<GB, 256>>>(x /*unused*/, W2, nullptr);
    k_aggr<true ><<<AGG_BLOCKS, 256>>>(b2, Wfc, bfc, out);
}

// round 7
// speedup vs baseline: 1.2573x; 1.2573x over previous
#include <cuda_runtime.h>
#include <mma.h>

using namespace nvcuda;

#define N_NODES 100000
#define N_EDGES 1600000
#define IN_DIM  128
#define HID_DIM 64
#define GB      782          // ceil(N_NODES/128) gemm tile blocks
#define FB      1024         // fill blocks riding along with gemm1
#define SB      98           // scan blocks, < 148 SMs (all resident)
#define AGG_GRID 740         // 5 blocks/SM -> all resident, grid-stride warps

// ------------------------- device scratch (no allocs allowed) ---------------
// d_cnt / d_flag start zeroed (BSS) and are re-zeroed at the end of every call
// by the final aggregation kernel, so every invocation sees identical state.
__device__ int   d_cnt [N_NODES];                       // edge count per dst
__device__ int   d_rs  [N_NODES];                       // CSR row starts
__device__ int   d_fill[N_NODES];                       // fill cursors
__device__ float d_dinv[N_NODES];                       // 1/sqrt(deg) (deg=cnt+1)
__device__ int   d_csr [N_EDGES];                       // src ids bucketed by dst
__device__ __align__(16) float d_bufA[(size_t)N_NODES * HID_DIM]; // g = (A@W)*dinv
__device__ __align__(16) float d_bufB[(size_t)N_NODES * HID_DIM]; // activation
__device__ int   d_agg [SB];                            // scan block aggregates
__device__ int   d_flag[SB];                            // publish flags

// ------------------------- degree count -------------------------------------
__global__ void k_count(const int* __restrict__ dst) {
    int e = blockIdx.x * blockDim.x + threadIdx.x;
    if (e < N_EDGES) atomicAdd(&d_cnt[dst[e]], 1);
}

// ------------------------- single-pass scan (row starts + dinv) -------------
__global__ __launch_bounds__(256) void k_scan() {
    __shared__ int sm[256];
    __shared__ int sBase;
    int tid = threadIdx.x, bid = blockIdx.x;
    int base = bid * 1024 + tid * 4;
    int c[4], v[4];
    int s = 0;
#pragma unroll
    for (int j = 0; j < 4; ++j) {
        int idx = base + j;
        c[j] = (idx < N_NODES) ? d_cnt[idx] : 0;
        v[j] = s; s += c[j];
    }
    sm[tid] = s;
    __syncthreads();
#pragma unroll
    for (int off = 1; off < 256; off <<= 1) {
        int t = (tid >= off) ? sm[tid - off] : 0;
        __syncthreads();
        sm[tid] += t;
        __syncthreads();
    }
    if (tid == 0) {                                     // publish aggregate
        d_agg[bid] = sm[255];
        __threadfence();
        *((volatile int*)&d_flag[bid]) = 1;
    }
    if (tid < 32) {                                     // lookback: sum preds
        int acc = 0;
        for (int i = tid; i < bid; i += 32) {
            while (*((volatile int*)&d_flag[i]) == 0) {}
            acc += *((volatile int*)&d_agg[i]);
        }
#pragma unroll
        for (int off = 16; off; off >>= 1)
            acc += __shfl_down_sync(0xffffffffu, acc, off);
        if (tid == 0) sBase = acc;
    }
    __syncthreads();
    int excl = (tid == 0) ? 0 : sm[tid - 1];
    int off0 = sBase + excl;
#pragma unroll
    for (int j = 0; j < 4; ++j) {
        int idx = base + j;
        if (idx < N_NODES) {
            int r = off0 + v[j];
            d_rs[idx]   = r;
            d_fill[idx] = r;
            d_dinv[idx] = rsqrtf((float)(c[j] + 1));    // +1: self-loop
        }
    }
}

// ------------------------- TF32 GEMM (+ optional fused CSR fill) ------------
// C[r,:] = (A[r,:] @ W) * dinv[r].  Blocks >= GB (layer 1 only) do CSR fill
// instead -- fill and gemm1 both depend only on k_scan, not on each other.
#define SA_LD 40
#define SO_LD 68
#define SW_ELE (32 * 64)
#define SMEM_FLOATS 8704

template <int K, bool A_IS_PARAM, bool FUSE_FILL>
__global__ __launch_bounds__(256) void k_gemm_tf32(const float* __restrict__ Aparam,
                                                   const float* __restrict__ W,
                                                   const int* __restrict__ src,
                                                   const int* __restrict__ dst) {
    __shared__ __align__(16) float smem[SMEM_FLOATS];
    if (FUSE_FILL && blockIdx.x >= GB) {                // fused CSR fill
        int e0 = (blockIdx.x - GB) * 256 + threadIdx.x;
        for (int e = e0; e < N_EDGES; e += FB * 256) {
            int d = dst[e];
            int p = atomicAdd(&d_fill[d], 1);
            d_csr[p] = src[e];
        }
        return;
    }
    float* sW = smem;                                   // 32 x 64
    float* sA = smem + SW_ELE;                          // 128 x SA_LD
    const float* A = A_IS_PARAM ? Aparam : (const float*)d_bufB;

    int tid    = threadIdx.x;
    int warpId = tid >> 5;
    int r0     = blockIdx.x * 128;
    int wrow   = warpId * 16;

    wmma::fragment<wmma::matrix_a, 16, 16, 8, wmma::precision::tf32, wmma::row_major> fa;
    wmma::fragment<wmma::matrix_b, 16, 16, 8, wmma::precision::tf32, wmma::row_major> fb;
    wmma::fragment<wmma::accumulator, 16, 16, 8, float> fc[4];
#pragma unroll
    for (int n = 0; n < 4; ++n) wmma::fill_fragment(fc[n], 0.0f);

    for (int kc = 0; kc < K; kc += 32) {
#pragma unroll
        for (int u = 0; u < 2; ++u) {                   // W chunk: 32x64
            int idx = u * 256 + tid;
            float4 v = *(const float4*)&W[(size_t)kc * 64 + idx * 4];
            *(float4*)&sW[idx * 4] = v;
        }
#pragma unroll
        for (int u = 0; u < 4; ++u) {                   // A chunk: 128x32
            int idx = u * 256 + tid;
            int row = idx >> 3;
            int c4  = idx & 7;
            int r   = r0 + row;
            float4 v = make_float4(0.f, 0.f, 0.f, 0.f);
            if (r < N_NODES)
                v = *(const float4*)&A[(size_t)r * K + kc + c4 * 4];
            *(float4*)&sA[row * SA_LD + c4 * 4] = v;
        }
        __syncthreads();
#pragma unroll
        for (int kk = 0; kk < 32; kk += 8) {
            wmma::load_matrix_sync(fa, &sA[wrow * SA_LD + kk], SA_LD);
#pragma unroll
            for (int i = 0; i < fa.num_elements; ++i)
                fa.x[i] = wmma::__float_to_tf32(fa.x[i]);
#pragma unroll
            for (int n = 0; n < 4; ++n) {
                wmma::load_matrix_sync(fb, &sW[kk * 64 + n * 16], 64);
#pragma unroll
                for (int i = 0; i < fb.num_elements; ++i)
                    fb.x[i] = wmma::__float_to_tf32(fb.x[i]);
                wmma::mma_sync(fc[n], fa, fb, fc[n]);
            }
        }
        __syncthreads();
    }

    float* sOut = smem;                                 // 128 x SO_LD
#pragma unroll
    for (int n = 0; n < 4; ++n)
        wmma::store_matrix_sync(&sOut[wrow * SO_LD + n * 16], fc[n], SO_LD,
                                wmma::mem_row_major);
    __syncthreads();
#pragma unroll
    for (int u = 0; u < 8; ++u) {
        int idx = u * 256 + tid;
        int row = idx >> 4;
        int c4  = idx & 15;
        int r   = r0 + row;
        if (r < N_NODES) {
            float s = d_dinv[r];                        // dinv fused in epilogue
            float4 v = *(float4*)&sOut[row * SO_LD + c4 * 4];
            v.x *= s; v.y *= s; v.z *= s; v.w *= s;
            *(float4*)&d_bufA[(size_t)r * 64 + c4 * 4] = v;
        }
    }
}

// ------------------------- pull aggregation ---------------------------------
// Grid-stride warp-per-node (~17 nodes/warp: Poisson imbalance averages out).
// Pure gather-add: out[i] = relu(dinv_i*(sum g[src] + g[i]) + b), g has dinv
// pre-applied. FINAL: fuse 64->1 FC head + restore d_cnt/d_flag to zero.
template <bool FINAL>
__global__ __launch_bounds__(256) void k_aggr(const float* __restrict__ bias,
                                              const float* __restrict__ Wfc,
                                              const float* __restrict__ bfc,
                                              float* __restrict__ outp) {
    const int NW = AGG_GRID * 8;                        // total warps
    int gw   = (blockIdx.x * blockDim.x + threadIdx.x) >> 5;
    int lane = threadIdx.x & 31;
    const float2* __restrict__ gp = (const float2*)d_bufA;

    float2 bb = ((const float2*)bias)[lane];            // loop-invariant
    float2 wf;
    float  bf = 0.f;
    if (FINAL) { wf = ((const float2*)Wfc)[lane]; bf = bfc[0]; }

    for (int node = gw; node < N_NODES; node += NW) {
        int start = d_rs[node];
        int cnt   = d_cnt[node];

        float2 g = gp[(size_t)node * 32 + lane];        // self-loop term
        float2 a0 = g;
        float2 a1 = make_float2(0.f, 0.f);
        float2 a2 = make_float2(0.f, 0.f);
        float2 a3 = make_float2(0.f, 0.f);

        int t = 0;
        for (; t + 8 <= cnt; t += 8) {                  // 8-deep MLP
            int s0 = d_csr[start + t + 0];
            int s1 = d_csr[start + t + 1];
            int s2 = d_csr[start + t + 2];
            int s3 = d_csr[start + t + 3];
            int s4 = d_csr[start + t + 4];
            int s5 = d_csr[start + t + 5];
            int s6 = d_csr[start + t + 6];
            int s7 = d_csr[start + t + 7];
            float2 v0 = gp[(size_t)s0 * 32 + lane];
            float2 v1 = gp[(size_t)s1 * 32 + lane];
            float2 v2 = gp[(size_t)s2 * 32 + lane];
            float2 v3 = gp[(size_t)s3 * 32 + lane];
            float2 v4 = gp[(size_t)s4 * 32 + lane];
            float2 v5 = gp[(size_t)s5 * 32 + lane];
            float2 v6 = gp[(size_t)s6 * 32 + lane];
            float2 v7 = gp[(size_t)s7 * 32 + lane];
            a0.x += v0.x; a0.y += v0.y;  a1.x += v1.x; a1.y += v1.y;
            a2.x += v2.x; a2.y += v2.y;  a3.x += v3.x; a3.y += v3.y;
            a0.x += v4.x; a0.y += v4.y;  a1.x += v5.x; a1.y += v5.y;
            a2.x += v6.x; a2.y += v6.y;  a3.x += v7.x; a3.y += v7.y;
        }
        for (; t < cnt; ++t) {
            int s = d_csr[start + t];
            float2 v = gp[(size_t)s * 32 + lane];
            a0.x += v.x; a0.y += v.y;
        }

        float di = d_dinv[node];
        float h0 = fmaf(di, (a0.x + a1.x) + (a2.x + a3.x), bb.x);
        float h1 = fmaf(di, (a0.y + a1.y) + (a2.y + a3.y), bb.y);
        h0 = fmaxf(h0, 0.f);
        h1 = fmaxf(h1, 0.f);

        if (!FINAL) {
            ((float2*)d_bufB)[(size_t)node * 32 + lane] = make_float2(h0, h1);
        } else {
            float p = h0 * wf.x + h1 * wf.y;
#pragma unroll
            for (int off = 16; off; off >>= 1)
                p += __shfl_down_sync(0xffffffffu, p, off);
            if (lane == 0) outp[node] = p + bf;
            // restore invariant state for the next invocation
            if (lane == 1) d_cnt[node] = 0;
            if (lane == 2 && node < SB) d_flag[node] = 0;
        }
    }
}

// ------------------------- launch ------------------------------------------
extern "C" void kernel_launch(void* const* d_in, const int* in_sizes, int n_in,
                              void* d_out, int out_size) {
    const float* x    = (const float*)d_in[0];
    const int*   ei   = (const int*)d_in[1];   // JAX x64 disabled: int32
    const float* W1   = (const float*)d_in[2];
    const float* b1   = (const float*)d_in[3];
    const float* W2   = (const float*)d_in[4];
    const float* b2   = (const float*)d_in[5];
    const float* Wfc  = (const float*)d_in[6];
    const float* bfc  = (const float*)d_in[7];
    float*       out  = (float*)d_out;

    const int* srcp = ei;              // edge_index[0]
    const int* dstp = ei + N_EDGES;    // edge_index[1]

    const int EB = (N_EDGES + 255) / 256;

    k_count<<<EB, 256>>>(dstp);
    k_scan<<<SB, 256>>>();
    // gemm1 (dinv epilogue) fused with CSR fill -- both depend only on scan
    k_gemm_tf32<IN_DIM, true, true ><<<GB + FB, 256>>>(x, W1, srcp, dstp);
    k_aggr<false><<<AGG_GRID, 256>>>(b1, Wfc, bfc, out);
    // layer 2 + fused FC head (+ state restore)
    k_gemm_tf32<HID_DIM, false, false><<<GB, 256>>>(x /*unused*/, W2, nullptr, nullptr);
    k_aggr<true ><<<AGG_GRID, 256>>>(b2, Wfc, bfc, out);
}

// round 9
// speedup vs baseline: 1.3343x; 1.0612x over previous
#include <cuda_runtime.h>
#include <mma.h>

using namespace nvcuda;

#define N_NODES 100000
#define N_EDGES 1600000
#define NE4     (N_EDGES / 4)
#define IN_DIM  128
#define HID_DIM 64
#define GB      782          // ceil(N_NODES/128) gemm tile blocks
#define FB      1024         // fill blocks riding along with gemm1
#define SB      98           // scan blocks, < 148 SMs (all resident)
#define AGG_GRID 1184        // 8 blocks/SM -> 64 warps/SM (full occupancy)

// ------------------------- device scratch (no allocs allowed) ---------------
// d_cnt / d_flag start zeroed (BSS) and are re-zeroed at the end of every call
// by the final aggregation kernel, so every invocation sees identical state.
__device__ int   d_cnt [N_NODES];                       // edge count per dst
__device__ int   d_rs  [N_NODES];                       // CSR row starts
__device__ int   d_fill[N_NODES];                       // fill cursors
__device__ float d_dinv[N_NODES];                       // 1/sqrt(deg) (deg=cnt+1)
__device__ int   d_csr [N_EDGES];                       // src ids bucketed by dst
__device__ __align__(16) float d_bufA[(size_t)N_NODES * HID_DIM]; // g = (A@W)*dinv
__device__ __align__(16) float d_bufB[(size_t)N_NODES * HID_DIM]; // activation
__device__ int   d_agg [SB];                            // scan block aggregates
__device__ int   d_flag[SB];                            // publish flags

// ------------------------- degree count (int4 edge reads) -------------------
__global__ void k_count(const int4* __restrict__ dst4) {
    int i = blockIdx.x * blockDim.x + threadIdx.x;
    if (i < NE4) {                                      // guard: NE4 % 256 != 0
        int4 d = dst4[i];
        atomicAdd(&d_cnt[d.x], 1);
        atomicAdd(&d_cnt[d.y], 1);
        atomicAdd(&d_cnt[d.z], 1);
        atomicAdd(&d_cnt[d.w], 1);
    }
}

// ------------------------- single-pass scan (row starts + dinv) -------------
__global__ __launch_bounds__(256) void k_scan() {
    __shared__ int sm[256];
    __shared__ int sBase;
    int tid = threadIdx.x, bid = blockIdx.x;
    int base = bid * 1024 + tid * 4;
    int c[4], v[4];
    int s = 0;
#pragma unroll
    for (int j = 0; j < 4; ++j) {
        int idx = base + j;
        c[j] = (idx < N_NODES) ? d_cnt[idx] : 0;
        v[j] = s; s += c[j];
    }
    sm[tid] = s;
    __syncthreads();
#pragma unroll
    for (int off = 1; off < 256; off <<= 1) {
        int t = (tid >= off) ? sm[tid - off] : 0;
        __syncthreads();
        sm[tid] += t;
        __syncthreads();
    }
    if (tid == 0) {                                     // publish aggregate
        d_agg[bid] = sm[255];
        __threadfence();
        *((volatile int*)&d_flag[bid]) = 1;
    }
    if (tid < 32) {                                     // lookback: sum preds
        int acc = 0;
        for (int i = tid; i < bid; i += 32) {
            while (*((volatile int*)&d_flag[i]) == 0) {}
            acc += *((volatile int*)&d_agg[i]);
        }
#pragma unroll
        for (int off = 16; off; off >>= 1)
            acc += __shfl_down_sync(0xffffffffu, acc, off);
        if (tid == 0) sBase = acc;
    }
    __syncthreads();
    int excl = (tid == 0) ? 0 : sm[tid - 1];
    int off0 = sBase + excl;
#pragma unroll
    for (int j = 0; j < 4; ++j) {
        int idx = base + j;
        if (idx < N_NODES) {
            int r = off0 + v[j];
            d_rs[idx]   = r;
            d_fill[idx] = r;
            d_dinv[idx] = rsqrtf((float)(c[j] + 1));    // +1: self-loop
        }
    }
}

// ------------------------- TF32 GEMM (+ optional fused CSR fill) ------------
// C[r,:] = (A[r,:] @ W) * dinv[r].  Blocks >= GB (layer 1 only) do CSR fill
// instead -- fill and gemm1 both depend only on k_scan, not on each other.
#define SA_LD 40
#define SO_LD 68
#define SW_ELE (32 * 64)
#define SMEM_FLOATS 8704

template <int K, bool A_IS_PARAM, bool FUSE_FILL>
__global__ __launch_bounds__(256) void k_gemm_tf32(const float* __restrict__ Aparam,
                                                   const float* __restrict__ W,
                                                   const int4* __restrict__ src4,
                                                   const int4* __restrict__ dst4) {
    __shared__ __align__(16) float smem[SMEM_FLOATS];
    if (FUSE_FILL && blockIdx.x >= GB) {                // fused CSR fill
        int e0 = (blockIdx.x - GB) * 256 + threadIdx.x;
        for (int e = e0; e < NE4; e += FB * 256) {
            int4 d = dst4[e];
            int4 s = src4[e];
            d_csr[atomicAdd(&d_fill[d.x], 1)] = s.x;
            d_csr[atomicAdd(&d_fill[d.y], 1)] = s.y;
            d_csr[atomicAdd(&d_fill[d.z], 1)] = s.z;
            d_csr[atomicAdd(&d_fill[d.w], 1)] = s.w;
        }
        return;
    }
    float* sW = smem;                                   // 32 x 64
    float* sA = smem + SW_ELE;                          // 128 x SA_LD
    const float* A = A_IS_PARAM ? Aparam : (const float*)d_bufB;

    int tid    = threadIdx.x;
    int warpId = tid >> 5;
    int r0     = blockIdx.x * 128;
    int wrow   = warpId * 16;

    wmma::fragment<wmma::matrix_a, 16, 16, 8, wmma::precision::tf32, wmma::row_major> fa;
    wmma::fragment<wmma::matrix_b, 16, 16, 8, wmma::precision::tf32, wmma::row_major> fb;
    wmma::fragment<wmma::accumulator, 16, 16, 8, float> fc[4];
#pragma unroll
    for (int n = 0; n < 4; ++n) wmma::fill_fragment(fc[n], 0.0f);

    for (int kc = 0; kc < K; kc += 32) {
#pragma unroll
        for (int u = 0; u < 2; ++u) {                   // W chunk: 32x64
            int idx = u * 256 + tid;
            float4 v = *(const float4*)&W[(size_t)kc * 64 + idx * 4];
            *(float4*)&sW[idx * 4] = v;
        }
#pragma unroll
        for (int u = 0; u < 4; ++u) {                   // A chunk: 128x32
            int idx = u * 256 + tid;
            int row = idx >> 3;
            int c4  = idx & 7;
            int r   = r0 + row;
            float4 v = make_float4(0.f, 0.f, 0.f, 0.f);
            if (r < N_NODES)
                v = *(const float4*)&A[(size_t)r * K + kc + c4 * 4];
            *(float4*)&sA[row * SA_LD + c4 * 4] = v;
        }
        __syncthreads();
#pragma unroll
        for (int kk = 0; kk < 32; kk += 8) {
            wmma::load_matrix_sync(fa, &sA[wrow * SA_LD + kk], SA_LD);
#pragma unroll
            for (int i = 0; i < fa.num_elements; ++i)
                fa.x[i] = wmma::__float_to_tf32(fa.x[i]);
#pragma unroll
            for (int n = 0; n < 4; ++n) {
                wmma::load_matrix_sync(fb, &sW[kk * 64 + n * 16], 64);
#pragma unroll
                for (int i = 0; i < fb.num_elements; ++i)
                    fb.x[i] = wmma::__float_to_tf32(fb.x[i]);
                wmma::mma_sync(fc[n], fa, fb, fc[n]);
            }
        }
        __syncthreads();
    }

    float* sOut = smem;                                 // 128 x SO_LD
#pragma unroll
    for (int n = 0; n < 4; ++n)
        wmma::store_matrix_sync(&sOut[wrow * SO_LD + n * 16], fc[n], SO_LD,
                                wmma::mem_row_major);
    __syncthreads();
#pragma unroll
    for (int u = 0; u < 8; ++u) {
        int idx = u * 256 + tid;
        int row = idx >> 4;
        int c4  = idx & 15;
        int r   = r0 + row;
        if (r < N_NODES) {
            float s = d_dinv[r];                        // dinv fused in epilogue
            float4 v = *(float4*)&sOut[row * SO_LD + c4 * 4];
            v.x *= s; v.y *= s; v.z *= s; v.w *= s;
            *(float4*)&d_bufA[(size_t)r * 64 + c4 * 4] = v;
        }
    }
}

// ------------------------- pull aggregation ---------------------------------
// Grid-stride warp-per-node at full occupancy (8 blocks/SM, 64 warps).
// Pure gather-add: out[i] = relu(dinv_i*(sum g[src] + g[i]) + b), g has dinv
// pre-applied. FINAL: fuse 64->1 FC head + restore d_cnt/d_flag to zero.
template <bool FINAL>
__global__ __launch_bounds__(256, 8) void k_aggr(const float* __restrict__ bias,
                                                 const float* __restrict__ Wfc,
                                                 const float* __restrict__ bfc,
                                                 float* __restrict__ outp) {
    const int NW = AGG_GRID * 8;                        // total warps
    int gw   = (blockIdx.x * blockDim.x + threadIdx.x) >> 5;
    int lane = threadIdx.x & 31;
    const float2* __restrict__ gp = (const float2*)d_bufA + lane;

    float2 bb = ((const float2*)bias)[lane];            // loop-invariant
    float2 wf;
    float  bf = 0.f;
    if (FINAL) { wf = ((const float2*)Wfc)[lane]; bf = bfc[0]; }

    for (int node = gw; node < N_NODES; node += NW) {
        int start = d_rs[node];
        int cnt   = d_cnt[node];

        float2 a0 = gp[(unsigned)node * 32u];           // self-loop term
        float2 a1 = make_float2(0.f, 0.f);
        float2 a2 = make_float2(0.f, 0.f);
        float2 a3 = make_float2(0.f, 0.f);

        int t = 0;
        for (; t + 8 <= cnt; t += 8) {                  // 8-deep MLP
            unsigned s0 = (unsigned)d_csr[start + t + 0] * 32u;
            unsigned s1 = (unsigned)d_csr[start + t + 1] * 32u;
            unsigned s2 = (unsigned)d_csr[start + t + 2] * 32u;
            unsigned s3 = (unsigned)d_csr[start + t + 3] * 32u;
            unsigned s4 = (unsigned)d_csr[start + t + 4] * 32u;
            unsigned s5 = (unsigned)d_csr[start + t + 5] * 32u;
            unsigned s6 = (unsigned)d_csr[start + t + 6] * 32u;
            unsigned s7 = (unsigned)d_csr[start + t + 7] * 32u;
            float2 v0 = gp[s0];
            float2 v1 = gp[s1];
            float2 v2 = gp[s2];
            float2 v3 = gp[s3];
            float2 v4 = gp[s4];
            float2 v5 = gp[s5];
            float2 v6 = gp[s6];
            float2 v7 = gp[s7];
            a0.x += v0.x; a0.y += v0.y;  a1.x += v1.x; a1.y += v1.y;
            a2.x += v2.x; a2.y += v2.y;  a3.x += v3.x; a3.y += v3.y;
            a0.x += v4.x; a0.y += v4.y;  a1.x += v5.x; a1.y += v5.y;
            a2.x += v6.x; a2.y += v6.y;  a3.x += v7.x; a3.y += v7.y;
        }
        for (; t < cnt; ++t) {
            float2 v = gp[(unsigned)d_csr[start + t] * 32u];
            a0.x += v.x; a0.y += v.y;
        }

        float di = d_dinv[node];
        float h0 = fmaf(di, (a0.x + a1.x) + (a2.x + a3.x), bb.x);
        float h1 = fmaf(di, (a0.y + a1.y) + (a2.y + a3.y), bb.y);
        h0 = fmaxf(h0, 0.f);
        h1 = fmaxf(h1, 0.f);

        if (!FINAL) {
            *((float2*)d_bufB + lane + (unsigned)node * 32u) = make_float2(h0, h1);
        } else {
            float p = h0 * wf.x + h1 * wf.y;
#pragma unroll
            for (int off = 16; off; off >>= 1)
                p += __shfl_down_sync(0xffffffffu, p, off);
            if (lane == 0) outp[node] = p + bf;
            // restore invariant state for the next invocation
            if (lane == 1) d_cnt[node] = 0;
            if (lane == 2 && node < SB) d_flag[node] = 0;
        }
    }
}

// ------------------------- launch ------------------------------------------
extern "C" void kernel_launch(void* const* d_in, const int* in_sizes, int n_in,
                              void* d_out, int out_size) {
    const float* x    = (const float*)d_in[0];
    const int*   ei   = (const int*)d_in[1];   // JAX x64 disabled: int32
    const float* W1   = (const float*)d_in[2];
    const float* b1   = (const float*)d_in[3];
    const float* W2   = (const float*)d_in[4];
    const float* b2   = (const float*)d_in[5];
    const float* Wfc  = (const float*)d_in[6];
    const float* bfc  = (const float*)d_in[7];
    float*       out  = (float*)d_out;

    const int4* src4 = (const int4*)ei;                 // edge_index[0]
    const int4* dst4 = (const int4*)(ei + N_EDGES);     // edge_index[1]

    k_count<<<(NE4 + 255) / 256, 256>>>(dst4);          // ceil-div: cover ALL edges
    k_scan<<<SB, 256>>>();
    // gemm1 (dinv epilogue) fused with CSR fill -- both depend only on scan
    k_gemm_tf32<IN_DIM, true, true ><<<GB + FB, 256>>>(x, W1, src4, dst4);
    k_aggr<false><<<AGG_GRID, 256>>>(b1, Wfc, bfc, out);
    // layer 2 + fused FC head (+ state restore)
    k_gemm_tf32<HID_DIM, false, false><<<GB, 256>>>(x /*unused*/, W2, nullptr, nullptr);
    k_aggr<true ><<<AGG_GRID, 256>>>(b2, Wfc, bfc, out);
}

// round 10
// speedup vs baseline: 1.3587x; 1.0183x over previous
#include <cuda_runtime.h>
#include <mma.h>

using namespace nvcuda;

#define N_NODES 100000
#define N_EDGES 1600000
#define NE4     (N_EDGES / 4)
#define IN_DIM  128
#define HID_DIM 64
#define GB      782          // gemm tile blocks (ceil(N_NODES/128))
#define FB2     320          // fill blocks (after gemm in index order)
#define SB      98           // count+scan blocks (wave-1 resident)
#define AGG_GRID 1184        // 8 blocks/SM -> full occupancy for aggr

// ------------------------- device scratch (no allocs allowed) ---------------
// d_cnt / d_flag / d_sync* start zeroed (BSS) and are re-zeroed at the end of
// every call by the final aggregation kernel (invariant state).
__device__ int   d_cnt [N_NODES];                       // edge count per dst
__device__ int   d_rs  [N_NODES];                       // CSR row starts
__device__ int   d_fill[N_NODES];                       // fill cursors
__device__ float d_dinv[N_NODES];                       // 1/sqrt(deg) (deg=cnt+1)
__device__ int   d_csr [N_EDGES];                       // src ids bucketed by dst
__device__ __align__(16) float d_bufA[(size_t)N_NODES * HID_DIM]; // g = (A@W)*dinv
__device__ __align__(16) float d_bufB[(size_t)N_NODES * HID_DIM]; // activation
__device__ int   d_agg [SB];                            // scan block aggregates
__device__ int   d_flag[SB];                            // lookback publish flags
__device__ int   d_sync1;                               // count-done counter
__device__ int   d_sync2;                               // scan-done counter

// ------------------------- fused front kernel -------------------------------
// Roles by blockIdx.x:
//   [0, SB):        count edges -> barrier(98) -> scan -> publish scan_done
//   [SB, SB+GB):    gemm1 mainloop; spin on scan_done before dinv epilogue
//   [SB+GB, +FB2):  spin on scan_done, then CSR fill
#define SA_LD 40
#define SO_LD 68
#define SW_ELE (32 * 64)
#define SMEM_FLOATS 8704

template <int K, bool A_IS_PARAM, bool FRONT>
__global__ __launch_bounds__(256) void k_gemm_tf32(const float* __restrict__ Aparam,
                                                   const float* __restrict__ W,
                                                   const int4* __restrict__ src4,
                                                   const int4* __restrict__ dst4) {
    __shared__ __align__(16) float smem[SMEM_FLOATS];
    int tid = threadIdx.x;

    if (FRONT && blockIdx.x < SB) {
        // ---- role 1: count, barrier, scan ----
        int bid = blockIdx.x;
        for (int i = bid * 256 + tid; i < NE4; i += SB * 256) {
            int4 d = dst4[i];
            atomicAdd(&d_cnt[d.x], 1);
            atomicAdd(&d_cnt[d.y], 1);
            atomicAdd(&d_cnt[d.z], 1);
            atomicAdd(&d_cnt[d.w], 1);
        }
        __syncthreads();
        if (tid == 0) {                                 // barrier among 98 blocks
            __threadfence();
            atomicAdd(&d_sync1, 1);
            while (*((volatile int*)&d_sync1) < SB) {}
        }
        __syncthreads();

        int* sm = (int*)smem;                           // alias gemm smem
        int base = bid * 1024 + tid * 4;
        int c[4], v[4];
        int s = 0;
#pragma unroll
        for (int j = 0; j < 4; ++j) {
            int idx = base + j;
            c[j] = (idx < N_NODES) ? d_cnt[idx] : 0;
            v[j] = s; s += c[j];
        }
        sm[tid] = s;
        __syncthreads();
#pragma unroll
        for (int off = 1; off < 256; off <<= 1) {
            int t = (tid >= off) ? sm[tid - off] : 0;
            __syncthreads();
            sm[tid] += t;
            __syncthreads();
        }
        if (tid == 0) {                                 // publish block aggregate
            d_agg[bid] = sm[255];
            __threadfence();
            *((volatile int*)&d_flag[bid]) = 1;
        }
        if (tid == 255) sm[256] = 0;                    // sBase slot
        __syncthreads();
        if (tid < 32) {                                 // lookback: sum preds
            int acc = 0;
            for (int i = tid; i < bid; i += 32) {
                while (*((volatile int*)&d_flag[i]) == 0) {}
                acc += *((volatile int*)&d_agg[i]);
            }
#pragma unroll
            for (int off = 16; off; off >>= 1)
                acc += __shfl_down_sync(0xffffffffu, acc, off);
            if (tid == 0) sm[256] = acc;
        }
        __syncthreads();
        int excl = (tid == 0) ? 0 : sm[tid - 1];
        int off0 = sm[256] + excl;
#pragma unroll
        for (int j = 0; j < 4; ++j) {
            int idx = base + j;
            if (idx < N_NODES) {
                int r = off0 + v[j];
                d_rs[idx]   = r;
                d_fill[idx] = r;
                d_dinv[idx] = rsqrtf((float)(c[j] + 1));
            }
        }
        __syncthreads();
        if (tid == 0) {                                 // publish scan done
            __threadfence();
            atomicAdd(&d_sync2, 1);
        }
        return;
    }
    if (FRONT && blockIdx.x >= SB + GB) {
        // ---- role 3: CSR fill (after scan) ----
        if (tid == 0)
            while (*((volatile int*)&d_sync2) < SB) {}
        __syncthreads();
        int e0 = (blockIdx.x - SB - GB) * 256 + tid;
        for (int e = e0; e < NE4; e += FB2 * 256) {
            int4 d = dst4[e];
            int4 s = src4[e];
            d_csr[atomicAdd(&d_fill[d.x], 1)] = s.x;
            d_csr[atomicAdd(&d_fill[d.y], 1)] = s.y;
            d_csr[atomicAdd(&d_fill[d.z], 1)] = s.z;
            d_csr[atomicAdd(&d_fill[d.w], 1)] = s.w;
        }
        return;
    }

    // ---- role 2: TF32 GEMM, C[r,:] = (A[r,:] @ W) * dinv[r] ----
    float* sW = smem;                                   // 32 x 64
    float* sA = smem + SW_ELE;                          // 128 x SA_LD
    const float* A = A_IS_PARAM ? Aparam : (const float*)d_bufB;

    int warpId = tid >> 5;
    int r0     = (FRONT ? (blockIdx.x - SB) : blockIdx.x) * 128;
    int wrow   = warpId * 16;

    wmma::fragment<wmma::matrix_a, 16, 16, 8, wmma::precision::tf32, wmma::row_major> fa;
    wmma::fragment<wmma::matrix_b, 16, 16, 8, wmma::precision::tf32, wmma::row_major> fb;
    wmma::fragment<wmma::accumulator, 16, 16, 8, float> fc[4];
#pragma unroll
    for (int n = 0; n < 4; ++n) wmma::fill_fragment(fc[n], 0.0f);

    for (int kc = 0; kc < K; kc += 32) {
#pragma unroll
        for (int u = 0; u < 2; ++u) {                   // W chunk: 32x64
            int idx = u * 256 + tid;
            float4 v = *(const float4*)&W[(size_t)kc * 64 + idx * 4];
            *(float4*)&sW[idx * 4] = v;
        }
#pragma unroll
        for (int u = 0; u < 4; ++u) {                   // A chunk: 128x32
            int idx = u * 256 + tid;
            int row = idx >> 3;
            int c4  = idx & 7;
            int r   = r0 + row;
            float4 v = make_float4(0.f, 0.f, 0.f, 0.f);
            if (r < N_NODES)
                v = *(const float4*)&A[(size_t)r * K + kc + c4 * 4];
            *(float4*)&sA[row * SA_LD + c4 * 4] = v;
        }
        __syncthreads();
#pragma unroll
        for (int kk = 0; kk < 32; kk += 8) {
            wmma::load_matrix_sync(fa, &sA[wrow * SA_LD + kk], SA_LD);
#pragma unroll
            for (int i = 0; i < fa.num_elements; ++i)
                fa.x[i] = wmma::__float_to_tf32(fa.x[i]);
#pragma unroll
            for (int n = 0; n < 4; ++n) {
                wmma::load_matrix_sync(fb, &sW[kk * 64 + n * 16], 64);
#pragma unroll
                for (int i = 0; i < fb.num_elements; ++i)
                    fb.x[i] = wmma::__float_to_tf32(fb.x[i]);
                wmma::mma_sync(fc[n], fa, fb, fc[n]);
            }
        }
        __syncthreads();
    }

    float* sOut = smem;                                 // 128 x SO_LD
#pragma unroll
    for (int n = 0; n < 4; ++n)
        wmma::store_matrix_sync(&sOut[wrow * SO_LD + n * 16], fc[n], SO_LD,
                                wmma::mem_row_major);
    if (FRONT) {                                        // wait for dinv ready
        if (tid == 0)
            while (*((volatile int*)&d_sync2) < SB) {}
    }
    __syncthreads();
#pragma unroll
    for (int u = 0; u < 8; ++u) {
        int idx = u * 256 + tid;
        int row = idx >> 4;
        int c4  = idx & 15;
        int r   = r0 + row;
        if (r < N_NODES) {
            float s = d_dinv[r];                        // dinv fused in epilogue
            float4 v = *(float4*)&sOut[row * SO_LD + c4 * 4];
            v.x *= s; v.y *= s; v.z *= s; v.w *= s;
            *(float4*)&d_bufA[(size_t)r * 64 + c4 * 4] = v;
        }
    }
}

// ------------------------- pull aggregation ---------------------------------
// Grid-stride warp-per-node at full occupancy. Pure gather-add (L2-cap bound).
// FINAL: fuse 64->1 FC head + restore all invariant state to zero.
template <bool FINAL>
__global__ __launch_bounds__(256, 8) void k_aggr(const float* __restrict__ bias,
                                                 const float* __restrict__ Wfc,
                                                 const float* __restrict__ bfc,
                                                 float* __restrict__ outp) {
    const int NW = AGG_GRID * 8;                        // total warps
    int gw   = (blockIdx.x * blockDim.x + threadIdx.x) >> 5;
    int lane = threadIdx.x & 31;
    const float2* __restrict__ gp = (const float2*)d_bufA + lane;

    float2 bb = ((const float2*)bias)[lane];            // loop-invariant
    float2 wf;
    float  bf = 0.f;
    if (FINAL) { wf = ((const float2*)Wfc)[lane]; bf = bfc[0]; }

    for (int node = gw; node < N_NODES; node += NW) {
        int start = d_rs[node];
        int cnt   = d_cnt[node];

        float2 a0 = gp[(unsigned)node * 32u];           // self-loop term
        float2 a1 = make_float2(0.f, 0.f);
        float2 a2 = make_float2(0.f, 0.f);
        float2 a3 = make_float2(0.f, 0.f);

        int t = 0;
        for (; t + 8 <= cnt; t += 8) {                  // 8-deep MLP
            unsigned s0 = (unsigned)d_csr[start + t + 0] * 32u;
            unsigned s1 = (unsigned)d_csr[start + t + 1] * 32u;
            unsigned s2 = (unsigned)d_csr[start + t + 2] * 32u;
            unsigned s3 = (unsigned)d_csr[start + t + 3] * 32u;
            unsigned s4 = (unsigned)d_csr[start + t + 4] * 32u;
            unsigned s5 = (unsigned)d_csr[start + t + 5] * 32u;
            unsigned s6 = (unsigned)d_csr[start + t + 6] * 32u;
            unsigned s7 = (unsigned)d_csr[start + t + 7] * 32u;
            float2 v0 = gp[s0];
            float2 v1 = gp[s1];
            float2 v2 = gp[s2];
            float2 v3 = gp[s3];
            float2 v4 = gp[s4];
            float2 v5 = gp[s5];
            float2 v6 = gp[s6];
            float2 v7 = gp[s7];
            a0.x += v0.x; a0.y += v0.y;  a1.x += v1.x; a1.y += v1.y;
            a2.x += v2.x; a2.y += v2.y;  a3.x += v3.x; a3.y += v3.y;
            a0.x += v4.x; a0.y += v4.y;  a1.x += v5.x; a1.y += v5.y;
            a2.x += v6.x; a2.y += v6.y;  a3.x += v7.x; a3.y += v7.y;
        }
        for (; t < cnt; ++t) {
            float2 v = gp[(unsigned)d_csr[start + t] * 32u];
            a0.x += v.x; a0.y += v.y;
        }

        float di = d_dinv[node];
        float h0 = fmaf(di, (a0.x + a1.x) + (a2.x + a3.x), bb.x);
        float h1 = fmaf(di, (a0.y + a1.y) + (a2.y + a3.y), bb.y);
        h0 = fmaxf(h0, 0.f);
        h1 = fmaxf(h1, 0.f);

        if (!FINAL) {
            *((float2*)d_bufB + lane + (unsigned)node * 32u) = make_float2(h0, h1);
        } else {
            float p = h0 * wf.x + h1 * wf.y;
#pragma unroll
            for (int off = 16; off; off >>= 1)
                p += __shfl_down_sync(0xffffffffu, p, off);
            if (lane == 0) outp[node] = p + bf;
            // restore invariant state for the next invocation
            if (lane == 1) d_cnt[node] = 0;
            if (lane == 2 && node < SB) d_flag[node] = 0;
            if (lane == 3 && node == 0) d_sync1 = 0;
            if (lane == 4 && node == 0) d_sync2 = 0;
        }
    }
}

// ------------------------- launch ------------------------------------------
extern "C" void kernel_launch(void* const* d_in, const int* in_sizes, int n_in,
                              void* d_out, int out_size) {
    const float* x    = (const float*)d_in[0];
    const int*   ei   = (const int*)d_in[1];   // JAX x64 disabled: int32
    const float* W1   = (const float*)d_in[2];
    const float* b1   = (const float*)d_in[3];
    const float* W2   = (const float*)d_in[4];
    const float* b2   = (const float*)d_in[5];
    const float* Wfc  = (const float*)d_in[6];
    const float* bfc  = (const float*)d_in[7];
    float*       out  = (float*)d_out;

    const int4* src4 = (const int4*)ei;                 // edge_index[0]
    const int4* dst4 = (const int4*)(ei + N_EDGES);     // edge_index[1]

    // fused front: count+scan (blocks 0..97) || gemm1 (98..879) || fill (880..)
    k_gemm_tf32<IN_DIM, true, true ><<<SB + GB + FB2, 256>>>(x, W1, src4, dst4);
    k_aggr<false><<<AGG_GRID, 256>>>(b1, Wfc, bfc, out);
    // layer 2 + fused FC head (+ state restore)
    k_gemm_tf32<HID_DIM, false, false><<<GB, 256>>>(x /*unused*/, W2, nullptr, nullptr);
    k_aggr<true ><<<AGG_GRID, 256>>>(b2, Wfc, bfc, out);
}